// round 5
// baseline (speedup 1.0000x reference)
#include <cuda_runtime.h>
#include <cuda_bf16.h>
#include <cstdint>

#define NUM_BINS 5
#define DT_OFFSET 1
#define EV_PER_THREAD 4

// Scratch sized for 1280x720 (the dataset shape): 2 pol * H*W cells * 8 floats.
// Layout: scratch[((pos*H + y)*W + x) * 8 + 2*back_i + {0,1}] = {val_back, val_fwd}
// Pairs sit at even float offsets -> 8-byte aligned -> one red.global.add.v2.f32
// per event instead of two scalar atomics.
//
// g_scratch has no initializer -> zero-initialized at module load. The gather
// kernel writes zeros back after reading, so scratch is all-zero again at the
// start of every kernel_launch (graph-replay safe, no dedicated zero pass).
#define SCRATCH_CAP (2 * 1280 * 720 * 8)
__device__ float g_scratch[SCRATCH_CAP];

__device__ __forceinline__ void scatter_event_v2(float4 ev, float bt, float inv_dt,
                                                 int W, int H)
{
    float t = ev.x;
    int   x = (int)ev.y;
    int   y = (int)ev.z;
    int pos = (ev.w > 0.0f) ? 1 : 0;

    float tn    = (t - bt) * inv_dt;              // (t - bt) / dt
    float bin_f = (float)(NUM_BINS - 1) * tn;
    float back  = floorf(bin_f);
    float fwd_w = bin_f - back;
    int back_i  = (int)back;                      // 0..3 for this dataset

    float val_back = (1.0f - fwd_w) * tn;
    float val_fwd  = fwd_w * tn;

    int pc   = (pos * H + y) * W + x;
    float* addr = &g_scratch[pc * 8 + back_i * 2];
    asm volatile("red.global.add.v2.f32 [%0], {%1, %2};"
                 :: "l"(addr), "f"(val_back), "f"(val_fwd) : "memory");
}

__global__ void __launch_bounds__(256)
voxel_scatter_kernel(const float4* __restrict__ events,
                     int n,
                     const int* __restrict__ p_curr_time,
                     const int* __restrict__ p_delta_t,
                     const int* __restrict__ p_width,
                     const int* __restrict__ p_height)
{
    const int curr_time = *p_curr_time;
    const int delta_t   = *p_delta_t;
    const int W         = *p_width;
    const int H         = *p_height;

    const float bt = (float)(curr_time - delta_t);
    const float inv_dt = 1.0f / (float)(delta_t + DT_OFFSET);

    int base = (blockIdx.x * blockDim.x + threadIdx.x) * EV_PER_THREAD;

    if (base + EV_PER_THREAD <= n) {
        float4 ev[EV_PER_THREAD];
        #pragma unroll
        for (int j = 0; j < EV_PER_THREAD; j++)
            ev[j] = events[base + j];
        #pragma unroll
        for (int j = 0; j < EV_PER_THREAD; j++)
            scatter_event_v2(ev[j], bt, inv_dt, W, H);
    } else {
        for (int idx = base; idx < n; idx++)
            scatter_event_v2(events[idx], bt, inv_dt, W, H);
    }
}

// Fold 8 scratch slots per (pol,y,x) cell into the 5 output bins, then
// re-zero the scratch words just read (restores the all-zero invariant).
// out[(2b+pos)*plane + c] = slot[b].back + slot[b-1].fwd
__global__ void __launch_bounds__(256)
gather_kernel(float* __restrict__ out, int plane /* H*W */)
{
    int pc = blockIdx.x * blockDim.x + threadIdx.x;
    int ncells = 2 * plane;
    if (pc >= ncells) return;

    float4* s = reinterpret_cast<float4*>(g_scratch) + pc * 2;
    float4 lo = s[0];   // slot0.back, slot0.fwd, slot1.back, slot1.fwd
    float4 hi = s[1];   // slot2.back, slot2.fwd, slot3.back, slot3.fwd

    float4 z = make_float4(0.f, 0.f, 0.f, 0.f);
    s[0] = z;
    s[1] = z;

    int pos = (pc >= plane) ? 1 : 0;
    int c   = pc - pos * plane;
    float* o = out + pos * plane + c;
    const int bs = 2 * plane;           // bin stride in output

    o[0 * bs] = lo.x;                   // bin0: back(slot0)
    o[1 * bs] = lo.z + lo.y;            // bin1: back(1) + fwd(0)
    o[2 * bs] = hi.x + lo.w;            // bin2: back(2) + fwd(1)
    o[3 * bs] = hi.z + hi.y;            // bin3: back(3) + fwd(2)
    o[4 * bs] = hi.w;                   // bin4: fwd(3)
}

// ---- Fallback (arbitrary dims): direct scalar-atomic path ----
__device__ __forceinline__ void process_event_direct(float4 ev, float bt, float inv_dt,
                                                     int W, int H, int bin_stride,
                                                     float* __restrict__ out)
{
    float t = ev.x;
    int   x = (int)ev.y;
    int   y = (int)ev.z;
    int pos = (ev.w > 0.0f) ? 1 : 0;

    float tn    = (t - bt) * inv_dt;
    float bin_f = (float)(NUM_BINS - 1) * tn;
    float back  = floorf(bin_f);
    float fwd_w = bin_f - back;
    int back_i  = (int)back;

    float val_back = (1.0f - fwd_w) * tn;
    float val_fwd  = fwd_w * tn;

    int flat_back = ((back_i * 2 + pos) * H + y) * W + x;
    atomicAdd(&out[flat_back],              val_back);
    atomicAdd(&out[flat_back + bin_stride], val_fwd);
}

__global__ void __launch_bounds__(256)
voxel_grid_direct_kernel(const float4* __restrict__ events, int n,
                         const int* __restrict__ p_curr_time,
                         const int* __restrict__ p_delta_t,
                         const int* __restrict__ p_width,
                         const int* __restrict__ p_height,
                         float* __restrict__ out)
{
    const int curr_time = *p_curr_time;
    const int delta_t   = *p_delta_t;
    const int W         = *p_width;
    const int H         = *p_height;
    const float bt = (float)(curr_time - delta_t);
    const float inv_dt = 1.0f / (float)(delta_t + DT_OFFSET);
    const int bin_stride = 2 * H * W;

    int base = (blockIdx.x * blockDim.x + threadIdx.x) * EV_PER_THREAD;
    if (base + EV_PER_THREAD <= n) {
        float4 ev[EV_PER_THREAD];
        #pragma unroll
        for (int j = 0; j < EV_PER_THREAD; j++) ev[j] = events[base + j];
        #pragma unroll
        for (int j = 0; j < EV_PER_THREAD; j++)
            process_event_direct(ev[j], bt, inv_dt, W, H, bin_stride, out);
    } else {
        for (int idx = base; idx < n; idx++)
            process_event_direct(events[idx], bt, inv_dt, W, H, bin_stride, out);
    }
}

extern "C" void kernel_launch(void* const* d_in, const int* in_sizes, int n_in,
                              void* d_out, int out_size)
{
    const float4* events = (const float4*)d_in[0];
    const int* curr_time = (const int*)d_in[1];
    const int* delta_t   = (const int*)d_in[2];
    const int* width     = (const int*)d_in[3];
    const int* height    = (const int*)d_in[4];
    float* out = (float*)d_out;

    int n = in_sizes[0] / 4;   // events has N*4 float elements

    // out_size = NUM_BINS*2*H*W  ->  plane = H*W
    int plane = out_size / (NUM_BINS * 2);
    int scratch_floats = 2 * plane * 8;

    const int threads = 256;
    int ev_per_block = threads * EV_PER_THREAD;
    int ev_blocks = (n + ev_per_block - 1) / ev_per_block;

    if (scratch_floats <= SCRATCH_CAP) {
        // 1) scatter with one v2 red per event (scratch is all-zero on entry:
        //    zero-initialized at load, re-zeroed by gather on every launch)
        voxel_scatter_kernel<<<ev_blocks, threads>>>(events, n,
                                                     curr_time, delta_t,
                                                     width, height);
        // 2) gather scratch -> out, re-zero scratch (fully writes out)
        int ncells = 2 * plane;
        int gb = (ncells + threads - 1) / threads;
        gather_kernel<<<gb, threads>>>(out, plane);
    } else {
        cudaMemsetAsync(d_out, 0, (size_t)out_size * sizeof(float), 0);
        voxel_grid_direct_kernel<<<ev_blocks, threads>>>(events, n,
                                                         curr_time, delta_t,
                                                         width, height, out);
    }
}

// round 9
// speedup vs baseline: 1.2314x; 1.2314x over previous
#include <cuda_runtime.h>
#include <cuda_bf16.h>
#include <cstdint>

#define NUM_BINS 5
#define DT_OFFSET 1
#define EV_PER_THREAD 4

// Scratch: 2 pol * H*W cells * 8 floats.
// Layout: scratch[((pos*H + y)*W + x) * 8 + 2*back_i + {0,1}] = {val_back, val_fwd}
// Pairs at even float offsets -> 8B aligned -> one red.global.add.v2.f32/event.
#define SCRATCH_CAP (2 * 1280 * 720 * 8)
__device__ float g_scratch[SCRATCH_CAP];

// Wide zero: 4 x float4 = 64B per thread per iteration, grid-stride.
__global__ void __launch_bounds__(256)
zero_scratch_kernel(int n16 /* count of float4x4 groups */)
{
    int i = blockIdx.x * blockDim.x + threadIdx.x;
    int stride = gridDim.x * blockDim.x;
    float4* p = reinterpret_cast<float4*>(g_scratch);
    float4 z = make_float4(0.f, 0.f, 0.f, 0.f);
    for (; i < n16; i += stride) {
        float4* q = p + (size_t)i * 4;
        q[0] = z; q[1] = z; q[2] = z; q[3] = z;
    }
}

__device__ __forceinline__ void scatter_event_v2(float4 ev, float bt, float inv_dt,
                                                 int W, int H)
{
    float t = ev.x;
    int   x = (int)ev.y;
    int   y = (int)ev.z;
    int pos = (ev.w > 0.0f) ? 1 : 0;

    float tn    = (t - bt) * inv_dt;              // (t - bt) / dt
    float bin_f = (float)(NUM_BINS - 1) * tn;
    float back  = floorf(bin_f);
    float fwd_w = bin_f - back;
    int back_i  = (int)back;                      // 0..3 for this dataset

    float val_back = (1.0f - fwd_w) * tn;
    float val_fwd  = fwd_w * tn;

    int pc   = (pos * H + y) * W + x;
    float* addr = &g_scratch[pc * 8 + back_i * 2];
    asm volatile("red.global.add.v2.f32 [%0], {%1, %2};"
                 :: "l"(addr), "f"(val_back), "f"(val_fwd) : "memory");
}

__global__ void __launch_bounds__(256)
voxel_scatter_kernel(const float4* __restrict__ events,
                     int n,
                     const int* __restrict__ p_curr_time,
                     const int* __restrict__ p_delta_t,
                     const int* __restrict__ p_width,
                     const int* __restrict__ p_height)
{
    const int curr_time = *p_curr_time;
    const int delta_t   = *p_delta_t;
    const int W         = *p_width;
    const int H         = *p_height;

    const float bt = (float)(curr_time - delta_t);
    const float inv_dt = 1.0f / (float)(delta_t + DT_OFFSET);

    int base = (blockIdx.x * blockDim.x + threadIdx.x) * EV_PER_THREAD;

    if (base + EV_PER_THREAD <= n) {
        float4 ev[EV_PER_THREAD];
        #pragma unroll
        for (int j = 0; j < EV_PER_THREAD; j++)
            ev[j] = events[base + j];
        #pragma unroll
        for (int j = 0; j < EV_PER_THREAD; j++)
            scatter_event_v2(ev[j], bt, inv_dt, W, H);
    } else {
        for (int idx = base; idx < n; idx++)
            scatter_event_v2(events[idx], bt, inv_dt, W, H);
    }
}

// Vectorized gather: each thread folds 4 consecutive cells.
// Reads 8 float4 (128B contiguous), writes 5 float4 (one per bin plane).
// out[(2b+pos)*plane + c] = slot[b].back + slot[b-1].fwd
__global__ void __launch_bounds__(256)
gather4_kernel(float* __restrict__ out, int plane /* H*W, %4==0 */)
{
    int tid = blockIdx.x * blockDim.x + threadIdx.x;
    int ncells4 = (2 * plane) >> 2;
    if (tid >= ncells4) return;

    int pc = tid * 4;                      // first of 4 consecutive cells
    const float4* s = reinterpret_cast<const float4*>(g_scratch) + (size_t)pc * 2;

    float4 v[8];
    #pragma unroll
    for (int j = 0; j < 8; j++) v[j] = s[j];

    // cell k: lo = v[2k], hi = v[2k+1]
    float4 b0, b1, b2, b3, b4;
    {
        float* p0 = &b0.x; float* p1 = &b1.x; float* p2 = &b2.x;
        float* p3 = &b3.x; float* p4 = &b4.x;
        #pragma unroll
        for (int k = 0; k < 4; k++) {
            float4 lo = v[2 * k];
            float4 hi = v[2 * k + 1];
            p0[k] = lo.x;           // bin0: back(0)
            p1[k] = lo.z + lo.y;    // bin1: back(1)+fwd(0)
            p2[k] = hi.x + lo.w;    // bin2: back(2)+fwd(1)
            p3[k] = hi.z + hi.y;    // bin3: back(3)+fwd(2)
            p4[k] = hi.w;           // bin4: fwd(3)
        }
    }

    int pos = (pc >= plane) ? 1 : 0;
    int c   = pc - pos * plane;
    float* o = out + (size_t)pos * plane + c;
    const size_t bs = 2 * (size_t)plane;   // bin stride in output

    *reinterpret_cast<float4*>(o + 0 * bs) = b0;
    *reinterpret_cast<float4*>(o + 1 * bs) = b1;
    *reinterpret_cast<float4*>(o + 2 * bs) = b2;
    *reinterpret_cast<float4*>(o + 3 * bs) = b3;
    *reinterpret_cast<float4*>(o + 4 * bs) = b4;
}

// ---- Fallback (arbitrary dims): direct scalar-atomic path ----
__device__ __forceinline__ void process_event_direct(float4 ev, float bt, float inv_dt,
                                                     int W, int H, int bin_stride,
                                                     float* __restrict__ out)
{
    float t = ev.x;
    int   x = (int)ev.y;
    int   y = (int)ev.z;
    int pos = (ev.w > 0.0f) ? 1 : 0;

    float tn    = (t - bt) * inv_dt;
    float bin_f = (float)(NUM_BINS - 1) * tn;
    float back  = floorf(bin_f);
    float fwd_w = bin_f - back;
    int back_i  = (int)back;

    float val_back = (1.0f - fwd_w) * tn;
    float val_fwd  = fwd_w * tn;

    int flat_back = ((back_i * 2 + pos) * H + y) * W + x;
    atomicAdd(&out[flat_back],              val_back);
    atomicAdd(&out[flat_back + bin_stride], val_fwd);
}

__global__ void __launch_bounds__(256)
voxel_grid_direct_kernel(const float4* __restrict__ events, int n,
                         const int* __restrict__ p_curr_time,
                         const int* __restrict__ p_delta_t,
                         const int* __restrict__ p_width,
                         const int* __restrict__ p_height,
                         float* __restrict__ out)
{
    const int curr_time = *p_curr_time;
    const int delta_t   = *p_delta_t;
    const int W         = *p_width;
    const int H         = *p_height;
    const float bt = (float)(curr_time - delta_t);
    const float inv_dt = 1.0f / (float)(delta_t + DT_OFFSET);
    const int bin_stride = 2 * H * W;

    int base = (blockIdx.x * blockDim.x + threadIdx.x) * EV_PER_THREAD;
    if (base + EV_PER_THREAD <= n) {
        float4 ev[EV_PER_THREAD];
        #pragma unroll
        for (int j = 0; j < EV_PER_THREAD; j++) ev[j] = events[base + j];
        #pragma unroll
        for (int j = 0; j < EV_PER_THREAD; j++)
            process_event_direct(ev[j], bt, inv_dt, W, H, bin_stride, out);
    } else {
        for (int idx = base; idx < n; idx++)
            process_event_direct(events[idx], bt, inv_dt, W, H, bin_stride, out);
    }
}

extern "C" void kernel_launch(void* const* d_in, const int* in_sizes, int n_in,
                              void* d_out, int out_size)
{
    const float4* events = (const float4*)d_in[0];
    const int* curr_time = (const int*)d_in[1];
    const int* delta_t   = (const int*)d_in[2];
    const int* width     = (const int*)d_in[3];
    const int* height    = (const int*)d_in[4];
    float* out = (float*)d_out;

    int n = in_sizes[0] / 4;   // events has N*4 float elements

    // out_size = NUM_BINS*2*H*W  ->  plane = H*W
    int plane = out_size / (NUM_BINS * 2);
    size_t scratch_floats = (size_t)2 * plane * 8;

    const int threads = 256;
    int ev_per_block = threads * EV_PER_THREAD;
    int ev_blocks = (n + ev_per_block - 1) / ev_per_block;

    if (scratch_floats <= SCRATCH_CAP && (plane % 4) == 0) {
        // 1) zero scratch (wide stores, grid-stride)
        int n16 = (int)(scratch_floats / 16);
        int zb = (n16 + threads - 1) / threads;
        if (zb > 2048) zb = 2048;
        zero_scratch_kernel<<<zb, threads>>>(n16);
        // 2) scatter with one v2 red per event
        voxel_scatter_kernel<<<ev_blocks, threads>>>(events, n,
                                                     curr_time, delta_t,
                                                     width, height);
        // 3) vectorized gather scratch -> out (fully writes out)
        int ncells4 = (2 * plane) / 4;
        int gb = (ncells4 + threads - 1) / threads;
        gather4_kernel<<<gb, threads>>>(out, plane);
    } else {
        cudaMemsetAsync(d_out, 0, (size_t)out_size * sizeof(float), 0);
        voxel_grid_direct_kernel<<<ev_blocks, threads>>>(events, n,
                                                         curr_time, delta_t,
                                                         width, height, out);
    }
}

// round 10
// speedup vs baseline: 1.2658x; 1.0279x over previous
#include <cuda_runtime.h>
#include <cuda_bf16.h>
#include <cstdint>

#define NUM_BINS 5
#define DT_OFFSET 1
#define EV_PER_THREAD 4

// Slot-planar scratch: 4 slot planes, each ncells cells * 2 floats {back, fwd}.
//   scratch[(back_i * ncells + pc) * 2 + {0,1}]    pc = (pos*H + y)*W + x
// Pair is 8B-aligned -> one red.global.add.v2.f32 per event.
// Slot-planar (not cell-major) so the gather reads each slot plane with
// lane-consecutive float4s -> fully coalesced LDG.128.
#define SCRATCH_CAP (2 * 1280 * 720 * 8)
__device__ float g_scratch[SCRATCH_CAP];

// Coalesced zero: adjacent lanes store adjacent float4 (R4-proven pattern).
__global__ void __launch_bounds__(256)
zero_scratch_kernel(int n4)
{
    int i = blockIdx.x * blockDim.x + threadIdx.x;
    int stride = gridDim.x * blockDim.x;
    float4* p = reinterpret_cast<float4*>(g_scratch);
    float4 z = make_float4(0.f, 0.f, 0.f, 0.f);
    for (; i < n4; i += stride) p[i] = z;
}

__device__ __forceinline__ void scatter_event_v2(float4 ev, float bt, float inv_dt,
                                                 int W, int H, int ncells)
{
    float t = ev.x;
    int   x = (int)ev.y;
    int   y = (int)ev.z;
    int pos = (ev.w > 0.0f) ? 1 : 0;

    float tn    = (t - bt) * inv_dt;              // (t - bt) / dt
    float bin_f = (float)(NUM_BINS - 1) * tn;
    float back  = floorf(bin_f);
    float fwd_w = bin_f - back;
    int back_i  = (int)back;                      // 0..3 for this dataset

    float val_back = (1.0f - fwd_w) * tn;
    float val_fwd  = fwd_w * tn;

    int pc = (pos * H + y) * W + x;
    float* addr = &g_scratch[((size_t)back_i * ncells + pc) * 2];
    asm volatile("red.global.add.v2.f32 [%0], {%1, %2};"
                 :: "l"(addr), "f"(val_back), "f"(val_fwd) : "memory");
}

__global__ void __launch_bounds__(256)
voxel_scatter_kernel(const float4* __restrict__ events,
                     int n,
                     const int* __restrict__ p_curr_time,
                     const int* __restrict__ p_delta_t,
                     const int* __restrict__ p_width,
                     const int* __restrict__ p_height)
{
    const int curr_time = *p_curr_time;
    const int delta_t   = *p_delta_t;
    const int W         = *p_width;
    const int H         = *p_height;
    const int ncells    = 2 * H * W;

    const float bt = (float)(curr_time - delta_t);
    const float inv_dt = 1.0f / (float)(delta_t + DT_OFFSET);

    int base = (blockIdx.x * blockDim.x + threadIdx.x) * EV_PER_THREAD;

    if (base + EV_PER_THREAD <= n) {
        float4 ev[EV_PER_THREAD];
        #pragma unroll
        for (int j = 0; j < EV_PER_THREAD; j++)
            ev[j] = events[base + j];
        #pragma unroll
        for (int j = 0; j < EV_PER_THREAD; j++)
            scatter_event_v2(ev[j], bt, inv_dt, W, H, ncells);
    } else {
        for (int idx = base; idx < n; idx++)
            scatter_event_v2(events[idx], bt, inv_dt, W, H, ncells);
    }
}

// Coalesced gather: thread t folds cells (2t, 2t+1).
// One float4 per slot plane (lane-consecutive -> coalesced), 5 float2 stores.
// out[(2b+pos)*plane + c] = slot[b].back + slot[b-1].fwd
__global__ void __launch_bounds__(256)
gather_kernel(float* __restrict__ out, int plane /* H*W, even */)
{
    int t = blockIdx.x * blockDim.x + threadIdx.x;
    if (t >= plane) return;                    // plane threads = ncells/2 pairs

    const int ncells = 2 * plane;
    const int plane4 = ncells / 2;             // float4s per slot plane
    const float4* s = reinterpret_cast<const float4*>(g_scratch);

    // slot b, cells 2t & 2t+1: {back(2t), fwd(2t), back(2t+1), fwd(2t+1)}
    float4 s0 = s[0 * plane4 + t];
    float4 s1 = s[1 * plane4 + t];
    float4 s2 = s[2 * plane4 + t];
    float4 s3 = s[3 * plane4 + t];

    int pc  = 2 * t;
    int pos = (pc >= plane) ? 1 : 0;
    int c   = pc - pos * plane;                // even (plane is even)
    float* o = out + (size_t)pos * plane + c;
    const size_t bs = 2 * (size_t)plane;       // bin stride in output

    *reinterpret_cast<float2*>(o + 0 * bs) = make_float2(s0.x,        s0.z);
    *reinterpret_cast<float2*>(o + 1 * bs) = make_float2(s1.x + s0.y, s1.z + s0.w);
    *reinterpret_cast<float2*>(o + 2 * bs) = make_float2(s2.x + s1.y, s2.z + s1.w);
    *reinterpret_cast<float2*>(o + 3 * bs) = make_float2(s3.x + s2.y, s3.z + s2.w);
    *reinterpret_cast<float2*>(o + 4 * bs) = make_float2(s3.y,        s3.w);
}

// ---- Fallback (arbitrary dims): direct scalar-atomic path ----
__device__ __forceinline__ void process_event_direct(float4 ev, float bt, float inv_dt,
                                                     int W, int H, int bin_stride,
                                                     float* __restrict__ out)
{
    float t = ev.x;
    int   x = (int)ev.y;
    int   y = (int)ev.z;
    int pos = (ev.w > 0.0f) ? 1 : 0;

    float tn    = (t - bt) * inv_dt;
    float bin_f = (float)(NUM_BINS - 1) * tn;
    float back  = floorf(bin_f);
    float fwd_w = bin_f - back;
    int back_i  = (int)back;

    float val_back = (1.0f - fwd_w) * tn;
    float val_fwd  = fwd_w * tn;

    int flat_back = ((back_i * 2 + pos) * H + y) * W + x;
    atomicAdd(&out[flat_back],              val_back);
    atomicAdd(&out[flat_back + bin_stride], val_fwd);
}

__global__ void __launch_bounds__(256)
voxel_grid_direct_kernel(const float4* __restrict__ events, int n,
                         const int* __restrict__ p_curr_time,
                         const int* __restrict__ p_delta_t,
                         const int* __restrict__ p_width,
                         const int* __restrict__ p_height,
                         float* __restrict__ out)
{
    const int curr_time = *p_curr_time;
    const int delta_t   = *p_delta_t;
    const int W         = *p_width;
    const int H         = *p_height;
    const float bt = (float)(curr_time - delta_t);
    const float inv_dt = 1.0f / (float)(delta_t + DT_OFFSET);
    const int bin_stride = 2 * H * W;

    int base = (blockIdx.x * blockDim.x + threadIdx.x) * EV_PER_THREAD;
    if (base + EV_PER_THREAD <= n) {
        float4 ev[EV_PER_THREAD];
        #pragma unroll
        for (int j = 0; j < EV_PER_THREAD; j++) ev[j] = events[base + j];
        #pragma unroll
        for (int j = 0; j < EV_PER_THREAD; j++)
            process_event_direct(ev[j], bt, inv_dt, W, H, bin_stride, out);
    } else {
        for (int idx = base; idx < n; idx++)
            process_event_direct(events[idx], bt, inv_dt, W, H, bin_stride, out);
    }
}

extern "C" void kernel_launch(void* const* d_in, const int* in_sizes, int n_in,
                              void* d_out, int out_size)
{
    const float4* events = (const float4*)d_in[0];
    const int* curr_time = (const int*)d_in[1];
    const int* delta_t   = (const int*)d_in[2];
    const int* width     = (const int*)d_in[3];
    const int* height    = (const int*)d_in[4];
    float* out = (float*)d_out;

    int n = in_sizes[0] / 4;   // events has N*4 float elements

    // out_size = NUM_BINS*2*H*W  ->  plane = H*W
    int plane = out_size / (NUM_BINS * 2);
    size_t scratch_floats = (size_t)8 * 2 * plane;   // 4 slots * ncells * 2

    const int threads = 256;
    int ev_per_block = threads * EV_PER_THREAD;
    int ev_blocks = (n + ev_per_block - 1) / ev_per_block;

    if (scratch_floats <= SCRATCH_CAP && (plane % 2) == 0) {
        // 1) zero scratch (coalesced float4 stores, grid-stride)
        int n4 = (int)(scratch_floats / 4);
        int zb = (n4 + threads - 1) / threads;
        if (zb > 4096) zb = 4096;
        zero_scratch_kernel<<<zb, threads>>>(n4);
        // 2) scatter with one v2 red per event
        voxel_scatter_kernel<<<ev_blocks, threads>>>(events, n,
                                                     curr_time, delta_t,
                                                     width, height);
        // 3) coalesced gather scratch -> out (fully writes out)
        int gt = plane;                       // one thread per cell pair
        int gb = (gt + threads - 1) / threads;
        gather_kernel<<<gb, threads>>>(out, plane);
    } else {
        cudaMemsetAsync(d_out, 0, (size_t)out_size * sizeof(float), 0);
        voxel_grid_direct_kernel<<<ev_blocks, threads>>>(events, n,
                                                         curr_time, delta_t,
                                                         width, height, out);
    }
}

// round 12
// speedup vs baseline: 1.3885x; 1.0969x over previous
#include <cuda_runtime.h>
#include <cuda_bf16.h>
#include <cstdint>

#define NUM_BINS 5
#define DT_OFFSET 1
#define EV_PER_THREAD 4

// Cell-major scratch (R4-proven): 2 pol * H*W cells * 8 floats.
// scratch[((pos*H + y)*W + x) * 8 + 2*back_i + {0,1}] = {val_back, val_fwd}
// Pairs at even float offsets -> 8B aligned -> one red.global.add.v2.f32/event.
#define SCRATCH_CAP (2 * 1280 * 720 * 8)
__device__ float g_scratch[SCRATCH_CAP];

__device__ __forceinline__ void scatter_event_v2(float4 ev, float bt, float inv_dt,
                                                 int W, int H)
{
    float t = ev.x;
    int   x = (int)ev.y;
    int   y = (int)ev.z;
    int pos = (ev.w > 0.0f) ? 1 : 0;

    float tn    = (t - bt) * inv_dt;              // (t - bt) / dt
    float bin_f = (float)(NUM_BINS - 1) * tn;
    float back  = floorf(bin_f);
    float fwd_w = bin_f - back;
    int back_i  = (int)back;                      // 0..3 for this dataset

    float val_back = (1.0f - fwd_w) * tn;
    float val_fwd  = fwd_w * tn;

    int pc   = (pos * H + y) * W + x;
    float* addr = &g_scratch[pc * 8 + back_i * 2];
    asm volatile("red.global.add.v2.f32 [%0], {%1, %2};"
                 :: "l"(addr), "f"(val_back), "f"(val_fwd) : "memory");
}

__global__ void __launch_bounds__(256)
voxel_scatter_kernel(const float4* __restrict__ events,
                     int n,
                     const int* __restrict__ p_curr_time,
                     const int* __restrict__ p_delta_t,
                     const int* __restrict__ p_width,
                     const int* __restrict__ p_height)
{
    const int curr_time = *p_curr_time;
    const int delta_t   = *p_delta_t;
    const int W         = *p_width;
    const int H         = *p_height;

    const float bt = (float)(curr_time - delta_t);
    const float inv_dt = 1.0f / (float)(delta_t + DT_OFFSET);

    int base = (blockIdx.x * blockDim.x + threadIdx.x) * EV_PER_THREAD;

    if (base + EV_PER_THREAD <= n) {
        float4 ev[EV_PER_THREAD];
        #pragma unroll
        for (int j = 0; j < EV_PER_THREAD; j++)
            ev[j] = events[base + j];
        #pragma unroll
        for (int j = 0; j < EV_PER_THREAD; j++)
            scatter_event_v2(ev[j], bt, inv_dt, W, H);
    } else {
        for (int idx = base; idx < n; idx++)
            scatter_event_v2(events[idx], bt, inv_dt, W, H);
    }
}

// R4-proven gather: one thread per (pol,y,x) cell. Loads 2 float4 per cell,
// 5 scalar stores -- consecutive threads hit consecutive floats per bin plane
// (coalesced stores). out[(2b+pos)*plane + c] = slot[b].back + slot[b-1].fwd
__global__ void __launch_bounds__(256)
gather_kernel(float* __restrict__ out, int plane /* H*W */)
{
    int pc = blockIdx.x * blockDim.x + threadIdx.x;
    int ncells = 2 * plane;
    if (pc >= ncells) return;

    const float4* s = reinterpret_cast<const float4*>(g_scratch) + pc * 2;
    float4 lo = s[0];   // slot0.back, slot0.fwd, slot1.back, slot1.fwd
    float4 hi = s[1];   // slot2.back, slot2.fwd, slot3.back, slot3.fwd

    int pos = (pc >= plane) ? 1 : 0;
    int c   = pc - pos * plane;
    float* o = out + pos * plane + c;
    const int bs = 2 * plane;           // bin stride in output

    o[0 * bs] = lo.x;                   // bin0: back(slot0)
    o[1 * bs] = lo.z + lo.y;            // bin1: back(1) + fwd(0)
    o[2 * bs] = hi.x + lo.w;            // bin2: back(2) + fwd(1)
    o[3 * bs] = hi.z + hi.y;            // bin3: back(3) + fwd(2)
    o[4 * bs] = hi.w;                   // bin4: fwd(3)
}

// ---- Fallback (arbitrary dims): direct scalar-atomic path ----
__device__ __forceinline__ void process_event_direct(float4 ev, float bt, float inv_dt,
                                                     int W, int H, int bin_stride,
                                                     float* __restrict__ out)
{
    float t = ev.x;
    int   x = (int)ev.y;
    int   y = (int)ev.z;
    int pos = (ev.w > 0.0f) ? 1 : 0;

    float tn    = (t - bt) * inv_dt;
    float bin_f = (float)(NUM_BINS - 1) * tn;
    float back  = floorf(bin_f);
    float fwd_w = bin_f - back;
    int back_i  = (int)back;

    float val_back = (1.0f - fwd_w) * tn;
    float val_fwd  = fwd_w * tn;

    int flat_back = ((back_i * 2 + pos) * H + y) * W + x;
    atomicAdd(&out[flat_back],              val_back);
    atomicAdd(&out[flat_back + bin_stride], val_fwd);
}

__global__ void __launch_bounds__(256)
voxel_grid_direct_kernel(const float4* __restrict__ events, int n,
                         const int* __restrict__ p_curr_time,
                         const int* __restrict__ p_delta_t,
                         const int* __restrict__ p_width,
                         const int* __restrict__ p_height,
                         float* __restrict__ out)
{
    const int curr_time = *p_curr_time;
    const int delta_t   = *p_delta_t;
    const int W         = *p_width;
    const int H         = *p_height;
    const float bt = (float)(curr_time - delta_t);
    const float inv_dt = 1.0f / (float)(delta_t + DT_OFFSET);
    const int bin_stride = 2 * H * W;

    int base = (blockIdx.x * blockDim.x + threadIdx.x) * EV_PER_THREAD;
    if (base + EV_PER_THREAD <= n) {
        float4 ev[EV_PER_THREAD];
        #pragma unroll
        for (int j = 0; j < EV_PER_THREAD; j++) ev[j] = events[base + j];
        #pragma unroll
        for (int j = 0; j < EV_PER_THREAD; j++)
            process_event_direct(ev[j], bt, inv_dt, W, H, bin_stride, out);
    } else {
        for (int idx = base; idx < n; idx++)
            process_event_direct(events[idx], bt, inv_dt, W, H, bin_stride, out);
    }
}

extern "C" void kernel_launch(void* const* d_in, const int* in_sizes, int n_in,
                              void* d_out, int out_size)
{
    const float4* events = (const float4*)d_in[0];
    const int* curr_time = (const int*)d_in[1];
    const int* delta_t   = (const int*)d_in[2];
    const int* width     = (const int*)d_in[3];
    const int* height    = (const int*)d_in[4];
    float* out = (float*)d_out;

    int n = in_sizes[0] / 4;   // events has N*4 float elements

    // out_size = NUM_BINS*2*H*W  ->  plane = H*W
    int plane = out_size / (NUM_BINS * 2);
    size_t scratch_floats = (size_t)2 * plane * 8;

    const int threads = 256;
    int ev_per_block = threads * EV_PER_THREAD;
    int ev_blocks = (n + ev_per_block - 1) / ev_per_block;

    if (scratch_floats <= SCRATCH_CAP) {
        // 1) zero scratch via driver memset node (fixed-function path)
        void* scratch_ptr = nullptr;
        cudaGetSymbolAddress(&scratch_ptr, g_scratch);
        cudaMemsetAsync(scratch_ptr, 0, scratch_floats * sizeof(float), 0);
        // 2) scatter with one v2 red per event
        voxel_scatter_kernel<<<ev_blocks, threads>>>(events, n,
                                                     curr_time, delta_t,
                                                     width, height);
        // 3) gather scratch -> out (fully writes out; no out memset needed)
        int ncells = 2 * plane;
        int gb = (ncells + threads - 1) / threads;
        gather_kernel<<<gb, threads>>>(out, plane);
    } else {
        cudaMemsetAsync(d_out, 0, (size_t)out_size * sizeof(float), 0);
        voxel_grid_direct_kernel<<<ev_blocks, threads>>>(events, n,
                                                         curr_time, delta_t,
                                                         width, height, out);
    }
}

// round 17
// speedup vs baseline: 1.4255x; 1.0266x over previous
#include <cuda_runtime.h>
#include <cuda_bf16.h>
#include <cstdint>

#define NUM_BINS 5
#define DT_OFFSET 1
#define EV_PER_THREAD 4

// Cell-major scratch (R4-proven): 2 pol * H*W cells * 8 floats.
// scratch[((pos*H + y)*W + x) * 8 + 2*back_i + {0,1}] = {val_back, val_fwd}
// Pairs at even float offsets -> 8B aligned -> one red.global.add.v2.f32/event.
#define SCRATCH_CAP (2 * 1280 * 720 * 8)
__device__ float g_scratch[SCRATCH_CAP];

// Coalesced zero: adjacent lanes store adjacent float4 (default policy:
// keep the zeroed lines L2-resident for the scatter's reds).
__global__ void __launch_bounds__(256)
zero_scratch_kernel(int n4)
{
    int i = blockIdx.x * blockDim.x + threadIdx.x;
    int stride = gridDim.x * blockDim.x;
    float4* p = reinterpret_cast<float4*>(g_scratch);
    float4 z = make_float4(0.f, 0.f, 0.f, 0.f);
    for (; i < n4; i += stride) p[i] = z;
}

__device__ __forceinline__ void scatter_event_v2(float4 ev, float bt, float inv_dt,
                                                 int W, int H)
{
    float t = ev.x;
    int   x = (int)ev.y;
    int   y = (int)ev.z;
    int pos = (ev.w > 0.0f) ? 1 : 0;

    float tn    = (t - bt) * inv_dt;              // (t - bt) / dt
    float bin_f = (float)(NUM_BINS - 1) * tn;
    float back  = floorf(bin_f);
    float fwd_w = bin_f - back;
    int back_i  = (int)back;                      // 0..3 for this dataset

    float val_back = (1.0f - fwd_w) * tn;
    float val_fwd  = fwd_w * tn;

    int pc   = (pos * H + y) * W + x;
    float* addr = &g_scratch[pc * 8 + back_i * 2];
    asm volatile("red.global.add.v2.f32 [%0], {%1, %2};"
                 :: "l"(addr), "f"(val_back), "f"(val_fwd) : "memory");
}

__global__ void __launch_bounds__(256)
voxel_scatter_kernel(const float4* __restrict__ events,
                     int n,
                     const int* __restrict__ p_curr_time,
                     const int* __restrict__ p_delta_t,
                     const int* __restrict__ p_width,
                     const int* __restrict__ p_height)
{
    const int curr_time = *p_curr_time;
    const int delta_t   = *p_delta_t;
    const int W         = *p_width;
    const int H         = *p_height;

    const float bt = (float)(curr_time - delta_t);
    const float inv_dt = 1.0f / (float)(delta_t + DT_OFFSET);

    int base = (blockIdx.x * blockDim.x + threadIdx.x) * EV_PER_THREAD;

    if (base + EV_PER_THREAD <= n) {
        float4 ev[EV_PER_THREAD];
        #pragma unroll
        for (int j = 0; j < EV_PER_THREAD; j++)
            ev[j] = __ldcs(&events[base + j]);   // streaming: don't pollute L2
        #pragma unroll
        for (int j = 0; j < EV_PER_THREAD; j++)
            scatter_event_v2(ev[j], bt, inv_dt, W, H);
    } else {
        for (int idx = base; idx < n; idx++)
            scatter_event_v2(__ldcs(&events[idx]), bt, inv_dt, W, H);
    }
}

// R4-proven gather: one thread per (pol,y,x) cell. Loads 2 float4 per cell
// (evict-first: scratch is dead after this), 5 coalesced scalar stores.
// out[(2b+pos)*plane + c] = slot[b].back + slot[b-1].fwd
__global__ void __launch_bounds__(256)
gather_kernel(float* __restrict__ out, int plane /* H*W */)
{
    int pc = blockIdx.x * blockDim.x + threadIdx.x;
    int ncells = 2 * plane;
    if (pc >= ncells) return;

    const float4* s = reinterpret_cast<const float4*>(g_scratch) + pc * 2;
    float4 lo = __ldcs(&s[0]);   // slot0.back, slot0.fwd, slot1.back, slot1.fwd
    float4 hi = __ldcs(&s[1]);   // slot2.back, slot2.fwd, slot3.back, slot3.fwd

    int pos = (pc >= plane) ? 1 : 0;
    int c   = pc - pos * plane;
    float* o = out + pos * plane + c;
    const int bs = 2 * plane;           // bin stride in output

    o[0 * bs] = lo.x;                   // bin0: back(slot0)
    o[1 * bs] = lo.z + lo.y;            // bin1: back(1) + fwd(0)
    o[2 * bs] = hi.x + lo.w;            // bin2: back(2) + fwd(1)
    o[3 * bs] = hi.z + hi.y;            // bin3: back(3) + fwd(2)
    o[4 * bs] = hi.w;                   // bin4: fwd(3)
}

// ---- Fallback (arbitrary dims): direct scalar-atomic path ----
__device__ __forceinline__ void process_event_direct(float4 ev, float bt, float inv_dt,
                                                     int W, int H, int bin_stride,
                                                     float* __restrict__ out)
{
    float t = ev.x;
    int   x = (int)ev.y;
    int   y = (int)ev.z;
    int pos = (ev.w > 0.0f) ? 1 : 0;

    float tn    = (t - bt) * inv_dt;
    float bin_f = (float)(NUM_BINS - 1) * tn;
    float back  = floorf(bin_f);
    float fwd_w = bin_f - back;
    int back_i  = (int)back;

    float val_back = (1.0f - fwd_w) * tn;
    float val_fwd  = fwd_w * tn;

    int flat_back = ((back_i * 2 + pos) * H + y) * W + x;
    atomicAdd(&out[flat_back],              val_back);
    atomicAdd(&out[flat_back + bin_stride], val_fwd);
}

__global__ void __launch_bounds__(256)
voxel_grid_direct_kernel(const float4* __restrict__ events, int n,
                         const int* __restrict__ p_curr_time,
                         const int* __restrict__ p_delta_t,
                         const int* __restrict__ p_width,
                         const int* __restrict__ p_height,
                         float* __restrict__ out)
{
    const int curr_time = *p_curr_time;
    const int delta_t   = *p_delta_t;
    const int W         = *p_width;
    const int H         = *p_height;
    const float bt = (float)(curr_time - delta_t);
    const float inv_dt = 1.0f / (float)(delta_t + DT_OFFSET);
    const int bin_stride = 2 * H * W;

    int base = (blockIdx.x * blockDim.x + threadIdx.x) * EV_PER_THREAD;
    if (base + EV_PER_THREAD <= n) {
        float4 ev[EV_PER_THREAD];
        #pragma unroll
        for (int j = 0; j < EV_PER_THREAD; j++) ev[j] = events[base + j];
        #pragma unroll
        for (int j = 0; j < EV_PER_THREAD; j++)
            process_event_direct(ev[j], bt, inv_dt, W, H, bin_stride, out);
    } else {
        for (int idx = base; idx < n; idx++)
            process_event_direct(events[idx], bt, inv_dt, W, H, bin_stride, out);
    }
}

extern "C" void kernel_launch(void* const* d_in, const int* in_sizes, int n_in,
                              void* d_out, int out_size)
{
    const float4* events = (const float4*)d_in[0];
    const int* curr_time = (const int*)d_in[1];
    const int* delta_t   = (const int*)d_in[2];
    const int* width     = (const int*)d_in[3];
    const int* height    = (const int*)d_in[4];
    float* out = (float*)d_out;

    int n = in_sizes[0] / 4;   // events has N*4 float elements

    // out_size = NUM_BINS*2*H*W  ->  plane = H*W
    int plane = out_size / (NUM_BINS * 2);
    size_t scratch_floats = (size_t)2 * plane * 8;

    const int threads = 256;
    int ev_per_block = threads * EV_PER_THREAD;
    int ev_blocks = (n + ev_per_block - 1) / ev_per_block;

    if (scratch_floats <= SCRATCH_CAP) {
        // 1) zero scratch (coalesced float4 stores, grid-stride)
        int n4 = (int)(scratch_floats / 4);
        int zb = (n4 + threads - 1) / threads;
        if (zb > 4096) zb = 4096;
        zero_scratch_kernel<<<zb, threads>>>(n4);
        // 2) scatter with one v2 red per event (streaming event loads)
        voxel_scatter_kernel<<<ev_blocks, threads>>>(events, n,
                                                     curr_time, delta_t,
                                                     width, height);
        // 3) gather scratch -> out (fully writes out; no out memset needed)
        int ncells = 2 * plane;
        int gb = (ncells + threads - 1) / threads;
        gather_kernel<<<gb, threads>>>(out, plane);
    } else {
        cudaMemsetAsync(d_out, 0, (size_t)out_size * sizeof(float), 0);
        voxel_grid_direct_kernel<<<ev_blocks, threads>>>(events, n,
                                                         curr_time, delta_t,
                                                         width, height, out);
    }
}